// round 17
// baseline (speedup 1.0000x reference)
#include <cuda_runtime.h>
#include <cuda_bf16.h>
#include <cuda_fp16.h>
#include <cstdint>

#define NMAX 20000
#define NPAD 20032          // padded to 64-node blocks for k_post
#define EMAX 320000
#define F 64
#define H 4
#define SCB 1024            // elements per scan block

// ------------------- scratch (static device globals; no allocation) -------------------
__device__ float   g_srad[NMAX * H];      // [n][h]
__device__ float   g_stan[NMAX * H];
__device__ float   g_vrad[H * F];         // w_proj @ radial_score
__device__ float   g_vtan[H * F];
__device__ float   g_A[NPAD * 512];       // per-receiver weighted-x sums [n][mat*256+h*64+f]
__device__ float   g_M[512 * 64];         // combined (1/4)·w_{mat,h} @ w_out

// CSR sort scratch
__device__ int     g_cnt[NMAX];
__device__ int     g_off[NMAX + 1];
__device__ int     g_cur[NMAX];
__device__ int     g_bsum[64];            // per-scan-block totals
__device__ int     g_ss[EMAX];            // sorted sender
__device__ float   g_sl[EMAX];            // sorted edge_len
__device__ float4  g_er[EMAX];            // slow path scratch
__device__ float4  g_et[EMAX];
__device__ float4  g_w1[EMAX];
__device__ float4  g_w2[EMAX];

// ------------------- helpers -------------------
__device__ __forceinline__ float softplus_f(float v) {
    return (v > 20.0f) ? v : log1pf(__expf(v));
}
__device__ __forceinline__ float sigmoid_f(float v) {
    return 1.0f / (1.0f + __expf(-v));
}
__device__ __forceinline__ float wred_max(float v) {
#pragma unroll
    for (int d = 16; d; d >>= 1) v = fmaxf(v, __shfl_xor_sync(0xffffffffu, v, d));
    return v;
}
__device__ __forceinline__ float wred_sum(float v) {
#pragma unroll
    for (int d = 16; d; d >>= 1) v += __shfl_xor_sync(0xffffffffu, v, d);
    return v;
}

// ------------------- K0: fused setup (prep-M | score vectors | zero counters) --
__global__ void k_setup(const float* __restrict__ wrad,
                        const float* __restrict__ wtan,
                        const float* __restrict__ wout,
                        const float* __restrict__ wprj,
                        const float* __restrict__ rscore,
                        const float* __restrict__ tscore,
                        int n_nodes) {
    int b = blockIdx.x;
    int tid = threadIdx.x;
    if (b < 8) {
        int mat = b >> 2, h = b & 3;
        const float* w = (mat ? wtan : wrad) + h * F * F;
        __shared__ float sw[F * F];
        __shared__ float so[F * F];
        for (int i = tid; i < F * F; i += 256) {
            sw[i] = w[i];
            so[i] = wout[i];
        }
        __syncthreads();
        for (int idx = tid; idx < F * F; idx += 256) {
            int f = idx >> 6, go = idx & 63;
            float s = 0.0f;
#pragma unroll
            for (int g = 0; g < F; g++) s += sw[f * F + g] * so[g * F + go];
            g_M[((mat * 256) + h * 64 + f) * 64 + go] = 0.25f * s;
        }
    } else if (b == 8) {
        int h = tid >> 6;                    // tid = h*64 + f
        const float* wp = wprj + tid * F;
        float a = 0.0f, c = 0.0f;
#pragma unroll
        for (int g = 0; g < F; g++) {
            float w = wp[g];
            a += w * rscore[h * F + g];
            c += w * tscore[h * F + g];
        }
        g_vrad[tid] = a;
        g_vtan[tid] = c;
    } else {
        int i = (b - 9) * 256 + tid;
        if (i < n_nodes) g_cnt[i] = 0;
    }
}

// ------------------- K1b: node scalars (smem-staged) -------------------
#define SNB 32
__global__ void __launch_bounds__(256) k_scal(const float* __restrict__ x,
                                              int n_nodes) {
    __shared__ float xs[SNB][72];
    __shared__ float vs[8][68];
    int tid = threadIdx.x;
    int base = blockIdx.x * SNB;

    for (int i = tid; i < SNB * 16; i += 256) {
        int nl = i >> 4, fq = i & 15;
        int n = base + nl;
        float4 v = (n < n_nodes) ? *(const float4*)&x[n * F + fq * 4]
                                 : make_float4(0.f, 0.f, 0.f, 0.f);
        *(float4*)&xs[nl][fq * 4] = v;
    }
    if (tid < 128) {
        int row = tid >> 4, fq = tid & 15;
        int mat = row >> 2, h = row & 3;
        const float* src = (mat ? g_vtan : g_vrad) + h * F;
        *(float4*)&vs[row][fq * 4] = *(const float4*)&src[fq * 4];
    }
    __syncthreads();

    int nl = tid >> 3, c = tid & 7;
    int mat = c >> 2, h = c & 3;
    int n = base + nl;
    if (n >= n_nodes) return;
    const float* xr = xs[nl];
    const float* vv = vs[c];
    float s = 0.0f;
#pragma unroll
    for (int fq = 0; fq < 16; fq++) {
        float4 xv = *(const float4*)&xr[fq * 4];
        float4 v4 = *(const float4*)&vv[fq * 4];
        s += xv.x * v4.x + xv.y * v4.y + xv.z * v4.z + xv.w * v4.w;
    }
    if (mat) g_stan[n * H + h] = s;
    else     g_srad[n * H + h] = s;
}

// ------------------- K3: histogram by receiver (4 edges/thread) -------------------
__global__ void k_hist(const int* __restrict__ ei, int n_edges, int n_nodes) {
    int i = blockIdx.x * blockDim.x + threadIdx.x;
    int e0 = i * 4;
    if (e0 >= n_edges) return;
    if (((n_edges & 3) == 0) && (e0 + 3 < n_edges)) {
        int4 r4 = *(const int4*)&ei[n_edges + e0];
        if ((unsigned)r4.x < (unsigned)n_nodes) atomicAdd(&g_cnt[r4.x], 1);
        if ((unsigned)r4.y < (unsigned)n_nodes) atomicAdd(&g_cnt[r4.y], 1);
        if ((unsigned)r4.z < (unsigned)n_nodes) atomicAdd(&g_cnt[r4.z], 1);
        if ((unsigned)r4.w < (unsigned)n_nodes) atomicAdd(&g_cnt[r4.w], 1);
    } else {
        int e1 = min(e0 + 4, n_edges);
        for (int e = e0; e < e1; e++) {
            int r = ei[n_edges + e];
            if ((unsigned)r < (unsigned)n_nodes) atomicAdd(&g_cnt[r], 1);
        }
    }
}

// ------------------- K4a: scan stage 1 -------------------
__global__ void __launch_bounds__(256) k_scan1(int n) {
    __shared__ int wsum[8];
    int b = blockIdx.x, t = threadIdx.x;
    int base = b * SCB + t * 4;

    int4 c = make_int4(0, 0, 0, 0);
    if (base + 3 < n) c = *(const int4*)&g_cnt[base];
    else {
        if (base + 0 < n) c.x = g_cnt[base + 0];
        if (base + 1 < n) c.y = g_cnt[base + 1];
        if (base + 2 < n) c.z = g_cnt[base + 2];
        if (base + 3 < n) c.w = g_cnt[base + 3];
    }
    int p0 = c.x, p1 = p0 + c.y, p2 = p1 + c.z, p3 = p2 + c.w;

    int lane = t & 31, wid = t >> 5;
    int incl = p3;
#pragma unroll
    for (int d = 1; d < 32; d <<= 1) {
        int v = __shfl_up_sync(0xffffffffu, incl, d);
        if (lane >= d) incl += v;
    }
    if (lane == 31) wsum[wid] = incl;
    __syncthreads();
    int wpre = 0;
    if (t < 8) {
        int v = wsum[t];
        int ws = v;
#pragma unroll
        for (int d = 1; d < 8; d <<= 1) {
            int u = __shfl_up_sync(0xffu, ws, d);
            if (t >= d) ws += u;
        }
        wsum[t] = ws - v;
        if (t == 7) g_bsum[b] = ws;
    }
    __syncthreads();
    wpre = wsum[wid];
    int toff = wpre + incl - p3;

    int4 o;
    o.x = toff;
    o.y = toff + p0;
    o.z = toff + p1;
    o.w = toff + p2;
    if (base + 3 < n) *(int4*)&g_off[base] = o;
    else {
        if (base + 0 < n) g_off[base + 0] = o.x;
        if (base + 1 < n) g_off[base + 1] = o.y;
        if (base + 2 < n) g_off[base + 2] = o.z;
        if (base + 3 < n) g_off[base + 3] = o.w;
    }
}

// ------------------- K4b: scan stage 2 -------------------
__global__ void __launch_bounds__(256) k_scan2(int n, int nblocks) {
    int b = blockIdx.x, t = threadIdx.x;
    int pre = 0;
    for (int i = 0; i < b; i++) pre += g_bsum[i];

    int base = b * SCB + t * 4;
    if (base < n) {
        if (base + 3 < n) {
            int4 o = *(const int4*)&g_off[base];
            o.x += pre; o.y += pre; o.z += pre; o.w += pre;
            *(int4*)&g_off[base] = o;
            *(int4*)&g_cur[base] = o;
        } else {
            for (int j = 0; j < 4 && base + j < n; j++) {
                int v = g_off[base + j] + pre;
                g_off[base + j] = v;
                g_cur[base + j] = v;
            }
        }
    }
    if (b == 0 && t == 0) {
        int total = 0;
        for (int i = 0; i < nblocks; i++) total += g_bsum[i];
        g_off[n] = total;
    }
}

// ------------------- K5: scatter edges into CSR order (4 edges/thread) ---------
__global__ void k_sort(const int* __restrict__ ei,
                       const float* __restrict__ elen,
                       int n_edges, int n_nodes) {
    int i = blockIdx.x * blockDim.x + threadIdx.x;
    int e0 = i * 4;
    if (e0 >= n_edges) return;
    if (((n_edges & 3) == 0) && (e0 + 3 < n_edges)) {
        int4   s4 = *(const int4*)&ei[e0];
        int4   r4 = *(const int4*)&ei[n_edges + e0];
        float4 l4 = *(const float4*)&elen[e0];
        int   sa[4] = {s4.x, s4.y, s4.z, s4.w};
        int   ra[4] = {r4.x, r4.y, r4.z, r4.w};
        float la[4] = {l4.x, l4.y, l4.z, l4.w};
#pragma unroll
        for (int j = 0; j < 4; j++) {
            if ((unsigned)sa[j] >= (unsigned)n_nodes ||
                (unsigned)ra[j] >= (unsigned)n_nodes) continue;
            int pos = atomicAdd(&g_cur[ra[j]], 1);
            g_ss[pos] = sa[j];
            g_sl[pos] = la[j];
        }
    } else {
        int e1 = min(e0 + 4, n_edges);
        for (int e = e0; e < e1; e++) {
            int s = ei[e], r = ei[n_edges + e];
            if ((unsigned)s >= (unsigned)n_nodes ||
                (unsigned)r >= (unsigned)n_nodes) continue;
            int pos = atomicAdd(&g_cur[r], 1);
            g_ss[pos] = s;
            g_sl[pos] = elen[e];
        }
    }
}

// ------------------- K6: per-receiver softmax + weighted-x aggregation ---------
// warp per receiver. Fast path (deg <= 32): whole softmax register-resident,
// one edge per lane, weights broadcast via shfl in the gather loop. Slow path
// (deg > 32, ~1e-4 of nodes at Poisson(16)): memory-staged passes.
__global__ void __launch_bounds__(256) k_main(const float* __restrict__ xp,
                                              const float* __restrict__ rdls,
                                              const float* __restrict__ rtb,
                                              const float* __restrict__ rtw,
                                              const float* __restrict__ mixb,
                                              const float* __restrict__ mixs,
                                              int n_nodes) {
    int r = (blockIdx.x * blockDim.x + threadIdx.x) >> 5;
    int lane = threadIdx.x & 31;
    if (r >= n_nodes) return;
    int beg = g_off[r], end = g_off[r + 1];
    int cnt = end - beg;

    float4* Ar4 = (float4*)&g_A[r * 512];   // channel c at c*16 + (f/4)
    int half = lane >> 4;        // 0 or 1
    int hl   = lane & 15;        // feature quad

    if (cnt == 0) {
        float4 z = make_float4(0.f, 0.f, 0.f, 0.f);
        int c0 = half * 4;
#pragma unroll
        for (int c = 0; c < 4; c++) Ar4[(c0 + c) * 16 + hl] = z;
        return;
    }

    float dist_scale = softplus_f(rdls[0]);
    float4 tb = *(const float4*)rtb;
    float4 tw = *(const float4*)rtw;
    float4 mb = *(const float4*)mixb;
    float4 ms = *(const float4*)mixs;
    float4 srr = *(const float4*)&g_srad[r * 4];
    float4 str = *(const float4*)&g_stan[r * 4];

    const float NEG = __int_as_float(0xff800000);
    const float4* Xp4 = (const float4*)xp;   // 16 float4 per node

    float4 A0 = {0,0,0,0}, A1 = {0,0,0,0}, A2 = {0,0,0,0}, A3 = {0,0,0,0};
    float4 A4 = {0,0,0,0}, A5 = {0,0,0,0}, A6 = {0,0,0,0}, A7 = {0,0,0,0};
    float W10, W11, W12, W13, W20, W21, W22, W23;

    if (cnt <= 32) {
        // ================= FAST PATH: register-resident =================
        bool act = lane < cnt;
        int   s   = 0;
        float len = 0.0f;
        float4 rl = {NEG, NEG, NEG, NEG}, tl = {NEG, NEG, NEG, NEG};
        if (act) {
            s   = g_ss[beg + lane];
            len = g_sl[beg + lane];
            float4 ss = *(const float4*)&g_srad[s * 4];
            float4 ts = *(const float4*)&g_stan[s * 4];
            float c = dist_scale * len;
            float t0 = softplus_f(tb.x + tw.x * len) + 1e-4f;
            float t1 = softplus_f(tb.y + tw.y * len) + 1e-4f;
            float t2 = softplus_f(tb.z + tw.z * len) + 1e-4f;
            float t3 = softplus_f(tb.w + tw.w * len) + 1e-4f;
            rl.x = (ss.x - srr.x - c) / t0;
            rl.y = (ss.y - srr.y - c) / t1;
            rl.z = (ss.z - srr.z - c) / t2;
            rl.w = (ss.w - srr.w - c) / t3;
            tl.x = ts.x - str.x;
            tl.y = ts.y - str.y;
            tl.z = ts.z - str.z;
            tl.w = ts.w - str.w;
        }
        float mr0 = wred_max(rl.x), mr1 = wred_max(rl.y);
        float mr2 = wred_max(rl.z), mr3 = wred_max(rl.w);
        float mt0 = wred_max(tl.x), mt1 = wred_max(tl.y);
        float mt2 = wred_max(tl.z), mt3 = wred_max(tl.w);

        float4 er = {0,0,0,0}, et = {0,0,0,0};
        if (act) {
            er.x = __expf(rl.x - mr0);
            er.y = __expf(rl.y - mr1);
            er.z = __expf(rl.z - mr2);
            er.w = __expf(rl.w - mr3);
            et.x = __expf(tl.x - mt0);
            et.y = __expf(tl.y - mt1);
            et.z = __expf(tl.z - mt2);
            et.w = __expf(tl.w - mt3);
        }
        float dr0 = 1.0f / (wred_sum(er.x) + 1e-9f);
        float dr1 = 1.0f / (wred_sum(er.y) + 1e-9f);
        float dr2 = 1.0f / (wred_sum(er.z) + 1e-9f);
        float dr3 = 1.0f / (wred_sum(er.w) + 1e-9f);
        float dt0 = 1.0f / (wred_sum(et.x) + 1e-9f);
        float dt1 = 1.0f / (wred_sum(et.y) + 1e-9f);
        float dt2 = 1.0f / (wred_sum(et.z) + 1e-9f);
        float dt3 = 1.0f / (wred_sum(et.w) + 1e-9f);

        float4 w1 = {0,0,0,0}, w2 = {0,0,0,0};
        if (act) {
            float g0 = sigmoid_f(mb.x + ms.x * len);
            float g1 = sigmoid_f(mb.y + ms.y * len);
            float g2 = sigmoid_f(mb.z + ms.z * len);
            float g3 = sigmoid_f(mb.w + ms.w * len);
            float b0 = g0 * er.x * dr0 + (1.0f - g0) * et.x * dt0;
            float b1 = g1 * er.y * dr1 + (1.0f - g1) * et.y * dt1;
            float b2 = g2 * er.z * dr2 + (1.0f - g2) * et.z * dt2;
            float b3 = g3 * er.w * dr3 + (1.0f - g3) * et.w * dt3;
            w1.x = b0 * g0; w2.x = b0 * (1.0f - g0);
            w1.y = b1 * g1; w2.y = b1 * (1.0f - g1);
            w1.z = b2 * g2; w2.z = b2 * (1.0f - g2);
            w1.w = b3 * g3; w2.w = b3 * (1.0f - g3);
        }
        W10 = wred_sum(w1.x); W11 = wred_sum(w1.y);
        W12 = wred_sum(w1.z); W13 = wred_sum(w1.w);
        W20 = wred_sum(w2.x); W21 = wred_sum(w2.y);
        W22 = wred_sum(w2.z); W23 = wred_sum(w2.w);

        // gather loop: uniform trip count, per-lane broadcast index
        int iters = (cnt + 1) >> 1;
        for (int j = 0; j < iters; j++) {
            int i = 2 * j + half;
            bool ok = i < cnt;
            int idx = ok ? i : 0;
            int   si  = __shfl_sync(0xffffffffu, s, idx);
            float v1x = __shfl_sync(0xffffffffu, w1.x, idx);
            float v1y = __shfl_sync(0xffffffffu, w1.y, idx);
            float v1z = __shfl_sync(0xffffffffu, w1.z, idx);
            float v1w = __shfl_sync(0xffffffffu, w1.w, idx);
            float v2x = __shfl_sync(0xffffffffu, w2.x, idx);
            float v2y = __shfl_sync(0xffffffffu, w2.y, idx);
            float v2z = __shfl_sync(0xffffffffu, w2.z, idx);
            float v2w = __shfl_sync(0xffffffffu, w2.w, idx);
            if (ok) {
                float4 xv = Xp4[si * 16 + hl];
                A0.x += v1x * xv.x; A0.y += v1x * xv.y; A0.z += v1x * xv.z; A0.w += v1x * xv.w;
                A1.x += v1y * xv.x; A1.y += v1y * xv.y; A1.z += v1y * xv.z; A1.w += v1y * xv.w;
                A2.x += v1z * xv.x; A2.y += v1z * xv.y; A2.z += v1z * xv.z; A2.w += v1z * xv.w;
                A3.x += v1w * xv.x; A3.y += v1w * xv.y; A3.z += v1w * xv.z; A3.w += v1w * xv.w;
                A4.x += v2x * xv.x; A4.y += v2x * xv.y; A4.z += v2x * xv.z; A4.w += v2x * xv.w;
                A5.x += v2y * xv.x; A5.y += v2y * xv.y; A5.z += v2y * xv.z; A5.w += v2y * xv.w;
                A6.x += v2z * xv.x; A6.y += v2z * xv.y; A6.z += v2z * xv.z; A6.w += v2z * xv.w;
                A7.x += v2w * xv.x; A7.y += v2w * xv.y; A7.z += v2w * xv.z; A7.w += v2w * xv.w;
            }
        }
    } else {
        // ================= SLOW PATH: memory-staged (rare) =================
        const float NEGc = NEG;
        float mr0 = NEGc, mr1 = NEGc, mr2 = NEGc, mr3 = NEGc;
        float mt0 = NEGc, mt1 = NEGc, mt2 = NEGc, mt3 = NEGc;
        for (int i = beg + lane; i < end; i += 32) {
            int s = g_ss[i];
            float len = g_sl[i];
            float4 ss = *(const float4*)&g_srad[s * 4];
            float4 ts = *(const float4*)&g_stan[s * 4];
            float c = dist_scale * len;
            float t0 = softplus_f(tb.x + tw.x * len) + 1e-4f;
            float t1 = softplus_f(tb.y + tw.y * len) + 1e-4f;
            float t2 = softplus_f(tb.z + tw.z * len) + 1e-4f;
            float t3 = softplus_f(tb.w + tw.w * len) + 1e-4f;
            float4 rl, tl;
            rl.x = (ss.x - srr.x - c) / t0;
            rl.y = (ss.y - srr.y - c) / t1;
            rl.z = (ss.z - srr.z - c) / t2;
            rl.w = (ss.w - srr.w - c) / t3;
            tl.x = ts.x - str.x;
            tl.y = ts.y - str.y;
            tl.z = ts.z - str.z;
            tl.w = ts.w - str.w;
            g_er[i] = rl;
            g_et[i] = tl;
            mr0 = fmaxf(mr0, rl.x); mr1 = fmaxf(mr1, rl.y);
            mr2 = fmaxf(mr2, rl.z); mr3 = fmaxf(mr3, rl.w);
            mt0 = fmaxf(mt0, tl.x); mt1 = fmaxf(mt1, tl.y);
            mt2 = fmaxf(mt2, tl.z); mt3 = fmaxf(mt3, tl.w);
        }
        mr0 = wred_max(mr0); mr1 = wred_max(mr1); mr2 = wred_max(mr2); mr3 = wred_max(mr3);
        mt0 = wred_max(mt0); mt1 = wred_max(mt1); mt2 = wred_max(mt2); mt3 = wred_max(mt3);

        float dr0 = 0, dr1 = 0, dr2 = 0, dr3 = 0;
        float dt0 = 0, dt1 = 0, dt2 = 0, dt3 = 0;
        for (int i = beg + lane; i < end; i += 32) {
            float4 rl = g_er[i];
            float4 tl = g_et[i];
            float4 er, et;
            er.x = __expf(rl.x - mr0);
            er.y = __expf(rl.y - mr1);
            er.z = __expf(rl.z - mr2);
            er.w = __expf(rl.w - mr3);
            et.x = __expf(tl.x - mt0);
            et.y = __expf(tl.y - mt1);
            et.z = __expf(tl.z - mt2);
            et.w = __expf(tl.w - mt3);
            g_er[i] = er;
            g_et[i] = et;
            dr0 += er.x; dr1 += er.y; dr2 += er.z; dr3 += er.w;
            dt0 += et.x; dt1 += et.y; dt2 += et.z; dt3 += et.w;
        }
        dr0 = wred_sum(dr0); dr1 = wred_sum(dr1); dr2 = wred_sum(dr2); dr3 = wred_sum(dr3);
        dt0 = wred_sum(dt0); dt1 = wred_sum(dt1); dt2 = wred_sum(dt2); dt3 = wred_sum(dt3);
        dr0 = 1.0f / (dr0 + 1e-9f); dr1 = 1.0f / (dr1 + 1e-9f);
        dr2 = 1.0f / (dr2 + 1e-9f); dr3 = 1.0f / (dr3 + 1e-9f);
        dt0 = 1.0f / (dt0 + 1e-9f); dt1 = 1.0f / (dt1 + 1e-9f);
        dt2 = 1.0f / (dt2 + 1e-9f); dt3 = 1.0f / (dt3 + 1e-9f);

        float s10 = 0, s11 = 0, s12 = 0, s13 = 0;
        float s20 = 0, s21 = 0, s22 = 0, s23 = 0;
        for (int i = beg + lane; i < end; i += 32) {
            float len = g_sl[i];
            float4 er = g_er[i];
            float4 et = g_et[i];
            float g0 = sigmoid_f(mb.x + ms.x * len);
            float g1 = sigmoid_f(mb.y + ms.y * len);
            float g2 = sigmoid_f(mb.z + ms.z * len);
            float g3 = sigmoid_f(mb.w + ms.w * len);
            float b0 = g0 * er.x * dr0 + (1.0f - g0) * et.x * dt0;
            float b1 = g1 * er.y * dr1 + (1.0f - g1) * et.y * dt1;
            float b2 = g2 * er.z * dr2 + (1.0f - g2) * et.z * dt2;
            float b3 = g3 * er.w * dr3 + (1.0f - g3) * et.w * dt3;
            float4 w1, w2;
            w1.x = b0 * g0; w2.x = b0 * (1.0f - g0);
            w1.y = b1 * g1; w2.y = b1 * (1.0f - g1);
            w1.z = b2 * g2; w2.z = b2 * (1.0f - g2);
            w1.w = b3 * g3; w2.w = b3 * (1.0f - g3);
            g_w1[i] = w1;
            g_w2[i] = w2;
            s10 += w1.x; s11 += w1.y; s12 += w1.z; s13 += w1.w;
            s20 += w2.x; s21 += w2.y; s22 += w2.z; s23 += w2.w;
        }
        W10 = wred_sum(s10); W11 = wred_sum(s11); W12 = wred_sum(s12); W13 = wred_sum(s13);
        W20 = wred_sum(s20); W21 = wred_sum(s21); W22 = wred_sum(s22); W23 = wred_sum(s23);

        for (int i = beg + half; i < end; i += 2) {
            int s = g_ss[i];
            float4 w1 = g_w1[i];
            float4 w2 = g_w2[i];
            float4 xv = Xp4[s * 16 + hl];
            A0.x += w1.x * xv.x; A0.y += w1.x * xv.y; A0.z += w1.x * xv.z; A0.w += w1.x * xv.w;
            A1.x += w1.y * xv.x; A1.y += w1.y * xv.y; A1.z += w1.y * xv.z; A1.w += w1.y * xv.w;
            A2.x += w1.z * xv.x; A2.y += w1.z * xv.y; A2.z += w1.z * xv.z; A2.w += w1.z * xv.w;
            A3.x += w1.w * xv.x; A3.y += w1.w * xv.y; A3.z += w1.w * xv.z; A3.w += w1.w * xv.w;
            A4.x += w2.x * xv.x; A4.y += w2.x * xv.y; A4.z += w2.x * xv.z; A4.w += w2.x * xv.w;
            A5.x += w2.y * xv.x; A5.y += w2.y * xv.y; A5.z += w2.y * xv.z; A5.w += w2.y * xv.w;
            A6.x += w2.z * xv.x; A6.y += w2.z * xv.y; A6.z += w2.z * xv.z; A6.w += w2.z * xv.w;
            A7.x += w2.w * xv.x; A7.y += w2.w * xv.y; A7.z += w2.w * xv.z; A7.w += w2.w * xv.w;
        }
    }

    // merge half-warps (xor-16 add, both halves end with full sums)
#define MERGE(A) \
    A.x += __shfl_xor_sync(0xffffffffu, A.x, 16); \
    A.y += __shfl_xor_sync(0xffffffffu, A.y, 16); \
    A.z += __shfl_xor_sync(0xffffffffu, A.z, 16); \
    A.w += __shfl_xor_sync(0xffffffffu, A.w, 16);
    MERGE(A0) MERGE(A1) MERGE(A2) MERGE(A3)
    MERGE(A4) MERGE(A5) MERGE(A6) MERGE(A7)
#undef MERGE

    // receiver correction (both halves compute identically)
    {
        float4 xr = Xp4[r * 16 + hl];
        A0.x -= W10 * xr.x; A0.y -= W10 * xr.y; A0.z -= W10 * xr.z; A0.w -= W10 * xr.w;
        A1.x -= W11 * xr.x; A1.y -= W11 * xr.y; A1.z -= W11 * xr.z; A1.w -= W11 * xr.w;
        A2.x -= W12 * xr.x; A2.y -= W12 * xr.y; A2.z -= W12 * xr.z; A2.w -= W12 * xr.w;
        A3.x -= W13 * xr.x; A3.y -= W13 * xr.y; A3.z -= W13 * xr.z; A3.w -= W13 * xr.w;
        A4.x -= W20 * xr.x; A4.y -= W20 * xr.y; A4.z -= W20 * xr.z; A4.w -= W20 * xr.w;
        A5.x -= W21 * xr.x; A5.y -= W21 * xr.y; A5.z -= W21 * xr.z; A5.w -= W21 * xr.w;
        A6.x -= W22 * xr.x; A6.y -= W22 * xr.y; A6.z -= W22 * xr.z; A6.w -= W22 * xr.w;
        A7.x -= W23 * xr.x; A7.y -= W23 * xr.y; A7.z -= W23 * xr.z; A7.w -= W23 * xr.w;
    }

    // write: half 0 -> channels 0..3 (radial), half 1 -> channels 4..7 (tangential)
    if (half == 0) {
        Ar4[0 * 16 + hl] = A0;
        Ar4[1 * 16 + hl] = A1;
        Ar4[2 * 16 + hl] = A2;
        Ar4[3 * 16 + hl] = A3;
    } else {
        Ar4[4 * 16 + hl] = A4;
        Ar4[5 * 16 + hl] = A5;
        Ar4[6 * 16 + hl] = A6;
        Ar4[7 * 16 + hl] = A7;
    }
}

// ------------------- K7: out = x + A @ M  (fused proj + head-mean + w_out) ----
#define PNB 64
__global__ void __launch_bounds__(256) k_post(const float* __restrict__ x,
                                              float* __restrict__ out,
                                              int n_nodes) {
    int tid = threadIdx.x;
    int ng  = tid >> 4;
    int goq = tid & 15;
    int n0 = blockIdx.x * PNB + ng * 4;

    const float4* Mp = (const float4*)g_M;
    float4 acc0 = {0,0,0,0}, acc1 = {0,0,0,0}, acc2 = {0,0,0,0}, acc3 = {0,0,0,0};

    const float* A0 = &g_A[(size_t)n0 * 512];

#pragma unroll 2
    for (int k = 0; k < 512; k += 4) {
        float4 m0 = __ldg(&Mp[(k + 0) * 16 + goq]);
        float4 m1 = __ldg(&Mp[(k + 1) * 16 + goq]);
        float4 m2 = __ldg(&Mp[(k + 2) * 16 + goq]);
        float4 m3 = __ldg(&Mp[(k + 3) * 16 + goq]);
        float4 a0 = *(const float4*)&A0[0 * 512 + k];
        float4 a1 = *(const float4*)&A0[1 * 512 + k];
        float4 a2 = *(const float4*)&A0[2 * 512 + k];
        float4 a3 = *(const float4*)&A0[3 * 512 + k];
        acc0.x += a0.x * m0.x + a0.y * m1.x + a0.z * m2.x + a0.w * m3.x;
        acc0.y += a0.x * m0.y + a0.y * m1.y + a0.z * m2.y + a0.w * m3.y;
        acc0.z += a0.x * m0.z + a0.y * m1.z + a0.z * m2.z + a0.w * m3.z;
        acc0.w += a0.x * m0.w + a0.y * m1.w + a0.z * m2.w + a0.w * m3.w;
        acc1.x += a1.x * m0.x + a1.y * m1.x + a1.z * m2.x + a1.w * m3.x;
        acc1.y += a1.x * m0.y + a1.y * m1.y + a1.z * m2.y + a1.w * m3.y;
        acc1.z += a1.x * m0.z + a1.y * m1.z + a1.z * m2.z + a1.w * m3.z;
        acc1.w += a1.x * m0.w + a1.y * m1.w + a1.z * m2.w + a1.w * m3.w;
        acc2.x += a2.x * m0.x + a2.y * m1.x + a2.z * m2.x + a2.w * m3.x;
        acc2.y += a2.x * m0.y + a2.y * m1.y + a2.z * m2.y + a2.w * m3.y;
        acc2.z += a2.x * m0.z + a2.y * m1.z + a2.z * m2.z + a2.w * m3.z;
        acc2.w += a2.x * m0.w + a2.y * m1.w + a2.z * m2.w + a2.w * m3.w;
        acc3.x += a3.x * m0.x + a3.y * m1.x + a3.z * m2.x + a3.w * m3.x;
        acc3.y += a3.x * m0.y + a3.y * m1.y + a3.z * m2.y + a3.w * m3.y;
        acc3.z += a3.x * m0.z + a3.y * m1.z + a3.z * m2.z + a3.w * m3.z;
        acc3.w += a3.x * m0.w + a3.y * m1.w + a3.z * m2.w + a3.w * m3.w;
    }

    float4 accs[4] = {acc0, acc1, acc2, acc3};
#pragma unroll
    for (int j = 0; j < 4; j++) {
        int n = n0 + j;
        if (n >= n_nodes) break;
        float4 xv = *(const float4*)&x[n * F + goq * 4];
        float4 o;
        o.x = xv.x + accs[j].x;
        o.y = xv.y + accs[j].y;
        o.z = xv.z + accs[j].z;
        o.w = xv.w + accs[j].w;
        *(float4*)&out[n * F + goq * 4] = o;
    }
}

// ------------------- launch -------------------
extern "C" void kernel_launch(void* const* d_in, const int* in_sizes, int n_in,
                              void* d_out, int out_size) {
    const float* x     = (const float*)d_in[0];
    const int*   ei    = (const int*)d_in[1];     // edge_index staged as int32, [2, E]
    // d_in[2] = edge_vec (unused by reference)
    const float* elen  = (const float*)d_in[3];
    const float* wprj  = (const float*)d_in[4];
    const float* wrad  = (const float*)d_in[5];
    const float* wtan  = (const float*)d_in[6];
    const float* rsc   = (const float*)d_in[7];
    const float* tsc   = (const float*)d_in[8];
    const float* rdls  = (const float*)d_in[9];
    const float* rtb   = (const float*)d_in[10];
    const float* rtw   = (const float*)d_in[11];
    const float* mixb  = (const float*)d_in[12];
    const float* mixs  = (const float*)d_in[13];
    const float* wout  = (const float*)d_in[14];
    float*       out   = (float*)d_out;

    int n_nodes = in_sizes[0] / F;
    int n_edges = in_sizes[3];

    k_setup<<<9 + (n_nodes + 255) / 256, 256>>>(wrad, wtan, wout,
                                                wprj, rsc, tsc, n_nodes);
    k_scal<<<(n_nodes + SNB - 1) / SNB, 256>>>(x, n_nodes);

    int ethreads = (n_edges + 3) / 4;
    k_hist<<<(ethreads + 255) / 256, 256>>>(ei, n_edges, n_nodes);

    int sblocks = (n_nodes + SCB - 1) / SCB;
    k_scan1<<<sblocks, 256>>>(n_nodes);
    k_scan2<<<sblocks, 256>>>(n_nodes, sblocks);

    k_sort<<<(ethreads + 255) / 256, 256>>>(ei, elen, n_edges, n_nodes);

    k_main<<<(n_nodes * 32 + 255) / 256, 256>>>(x, rdls, rtb, rtw, mixb, mixs, n_nodes);
    k_post<<<(n_nodes + PNB - 1) / PNB, 256>>>(x, out, n_nodes);
}